// round 1
// baseline (speedup 1.0000x reference)
#include <cuda_runtime.h>
#include <cuda_bf16.h>

#define NN   50000
#define EE   800000
#define NG   512
#define FIN  256
#define FH   128

// ---------------- scratch (static device globals; no allocation) ----------------
__device__ float g_bufA[NN * FH];          // 25.6 MB
__device__ float g_bufB[NN * FH];          // 25.6 MB (agg accumulator)
__device__ float g_bufC[NN * FH];          // 25.6 MB
__device__ float g_pool[NG * 2 * FH];      // concat [G, 256]: bu @0, td @128
__device__ float g_mlp[NG * 256];          // MLP hidden
__device__ int   g_deg[2 * NN];            // [0..NN) = indeg (dst), [NN..2NN) = outdeg (src)
__device__ float g_dinv[2 * NN];

// ---------------- utility kernels ----------------
__global__ void zero_f4(float* p, int n4) {
    int i = blockIdx.x * blockDim.x + threadIdx.x;
    if (i < n4) ((float4*)p)[i] = make_float4(0.f, 0.f, 0.f, 0.f);
}
__global__ void zero_i(int* p, int n) {
    int i = blockIdx.x * blockDim.x + threadIdx.x;
    if (i < n) p[i] = 0;
}
__global__ void deg_kernel(const int* __restrict__ src, const int* __restrict__ dst,
                           int* deg_in, int* deg_out, int e) {
    int i = blockIdx.x * blockDim.x + threadIdx.x;
    if (i < e) {
        atomicAdd(&deg_in[dst[i]], 1);
        atomicAdd(&deg_out[src[i]], 1);
    }
}
__global__ void dinv_kernel(const int* __restrict__ deg, float* __restrict__ dinv, int n) {
    int i = blockIdx.x * blockDim.x + threadIdx.x;
    if (i < n) dinv[i] = rsqrtf((float)deg[i] + 1.0f);
}

// ---------------- GEMM: C[M,N] = A[M,K] @ B[K,N] (+bias, +relu) ----------------
// Block: 256 threads, tile 64(M) x 128(N) x 32(K). Thread tile: 8 rows x 4 cols.
__global__ void gemm_kernel(const float* __restrict__ A, const float* __restrict__ B,
                            const float* __restrict__ bias, float* __restrict__ C,
                            int M, int K, int N, int doRelu) {
    __shared__ float As[32][64 + 4];   // [k][m], padded
    __shared__ float Bs[32][128];      // [k][n]

    const int m0  = blockIdx.x * 64;
    const int n0  = blockIdx.y * 128;
    const int tid = threadIdx.x;
    const int tx  = tid & 31;   // col group: cols tx*4..tx*4+3
    const int ty  = tid >> 5;   // row group: rows ty*8..ty*8+7

    float acc[8][4];
#pragma unroll
    for (int i = 0; i < 8; i++)
#pragma unroll
        for (int j = 0; j < 4; j++) acc[i][j] = 0.f;

    for (int k0 = 0; k0 < K; k0 += 32) {
        // A tile: 64x32 = 512 float4, 2 per thread (transposed store)
#pragma unroll
        for (int l = 0; l < 2; l++) {
            int idx = tid + l * 256;       // 0..511
            int row = idx >> 3;            // 0..63
            int c4  = idx & 7;             // 0..7
            float4 v = make_float4(0.f, 0.f, 0.f, 0.f);
            int gr = m0 + row;
            if (gr < M) v = *(const float4*)(A + (size_t)gr * K + k0 + c4 * 4);
            As[c4 * 4 + 0][row] = v.x;
            As[c4 * 4 + 1][row] = v.y;
            As[c4 * 4 + 2][row] = v.z;
            As[c4 * 4 + 3][row] = v.w;
        }
        // B tile: 32x128 = 1024 float4, 4 per thread
#pragma unroll
        for (int l = 0; l < 4; l++) {
            int idx = tid + l * 256;       // 0..1023
            int row = idx >> 5;            // 0..31
            int c4  = idx & 31;            // 0..31
            float4 v = *(const float4*)(B + (size_t)(k0 + row) * N + n0 + c4 * 4);
            *(float4*)&Bs[row][c4 * 4] = v;
        }
        __syncthreads();
#pragma unroll
        for (int k = 0; k < 32; k++) {
            float4 b = *(float4*)&Bs[k][tx * 4];
#pragma unroll
            for (int i = 0; i < 8; i++) {
                float a = As[k][ty * 8 + i];
                acc[i][0] = fmaf(a, b.x, acc[i][0]);
                acc[i][1] = fmaf(a, b.y, acc[i][1]);
                acc[i][2] = fmaf(a, b.z, acc[i][2]);
                acc[i][3] = fmaf(a, b.w, acc[i][3]);
            }
        }
        __syncthreads();
    }

    float4 bv = make_float4(0.f, 0.f, 0.f, 0.f);
    if (bias) bv = *(const float4*)(bias + n0 + tx * 4);
#pragma unroll
    for (int i = 0; i < 8; i++) {
        int gr = m0 + ty * 8 + i;
        if (gr < M) {
            float4 o;
            o.x = acc[i][0] + bv.x;
            o.y = acc[i][1] + bv.y;
            o.z = acc[i][2] + bv.z;
            o.w = acc[i][3] + bv.w;
            if (doRelu) {
                o.x = fmaxf(o.x, 0.f); o.y = fmaxf(o.y, 0.f);
                o.z = fmaxf(o.z, 0.f); o.w = fmaxf(o.w, 0.f);
            }
            *(float4*)(C + (size_t)gr * N + n0 + tx * 4) = o;
        }
    }
}

// ---------------- edge aggregation: agg[d] += h[s] * dinv[s]*dinv[d] ----------------
// One warp per edge (grid-stride). Lane handles 4 consecutive features (float4 gather).
__global__ void agg_kernel(const float* __restrict__ h, const int* __restrict__ src,
                           const int* __restrict__ dst, const float* __restrict__ dinv,
                           float* __restrict__ agg, int e) {
    int warp   = (blockIdx.x * blockDim.x + threadIdx.x) >> 5;
    int lane   = threadIdx.x & 31;
    int nwarps = (gridDim.x * blockDim.x) >> 5;
    for (int i = warp; i < e; i += nwarps) {
        int s = src[i];            // same addr across warp -> broadcast
        int d = dst[i];
        float nrm = dinv[s] * dinv[d];
        float4 v = *(const float4*)(h + (size_t)s * FH + lane * 4);
        float* o = agg + (size_t)d * FH + lane * 4;
        atomicAdd(o + 0, v.x * nrm);
        atomicAdd(o + 1, v.y * nrm);
        atomicAdd(o + 2, v.z * nrm);
        atomicAdd(o + 3, v.w * nrm);
    }
}

// ---------------- conv epilogue (in-place): h = act(agg + h*dinv^2 + bias) ----------
__global__ void epi_kernel(float* __restrict__ h, const float* __restrict__ agg,
                           const float* __restrict__ dinv, const float* __restrict__ bias,
                           int n, int doRelu) {
    int idx = blockIdx.x * blockDim.x + threadIdx.x;   // over n*32 float4s
    if (idx >= n * (FH / 4)) return;
    int node = idx >> 5;
    int c4   = (idx & 31) * 4;
    float di = dinv[node];
    float d2 = di * di;
    float4 hv = ((const float4*)h)[idx];
    float4 av = ((const float4*)agg)[idx];
    float4 bv = *(const float4*)(bias + c4);
    float4 o;
    o.x = av.x + hv.x * d2 + bv.x;
    o.y = av.y + hv.y * d2 + bv.y;
    o.z = av.z + hv.z * d2 + bv.z;
    o.w = av.w + hv.w * d2 + bv.w;
    if (doRelu) {
        o.x = fmaxf(o.x, 0.f); o.y = fmaxf(o.y, 0.f);
        o.z = fmaxf(o.z, 0.f); o.w = fmaxf(o.w, 0.f);
    }
    ((float4*)h)[idx] = o;
}

// ---------------- global add pool into concat buffer ----------------
// One warp per node; lane handles 4 features. pool row stride = 256, col offset selects branch.
__global__ void pool_kernel(const float* __restrict__ h, const int* __restrict__ batch,
                            float* __restrict__ pool, int n, int coloff) {
    int warp   = (blockIdx.x * blockDim.x + threadIdx.x) >> 5;
    int lane   = threadIdx.x & 31;
    int nwarps = (gridDim.x * blockDim.x) >> 5;
    for (int i = warp; i < n; i += nwarps) {
        int g = batch[i];
        float4 v = *(const float4*)(h + (size_t)i * FH + lane * 4);
        float* o = pool + (size_t)g * (2 * FH) + coloff + lane * 4;
        atomicAdd(o + 0, v.x);
        atomicAdd(o + 1, v.y);
        atomicAdd(o + 2, v.z);
        atomicAdd(o + 3, v.w);
    }
}

// ---------------- host-side branch driver ----------------
static void run_branch(const float* x, const int* s, const int* d, const float* dinv,
                       const float* W1, const float* b1, const float* W2, const float* b2,
                       const int* batch,
                       float* bufA, float* bufB, float* bufC, float* pool, int coloff) {
    const int gemmGridM = (NN + 63) / 64;
    const int n4  = NN * (FH / 4);
    const int zb  = (n4 + 255) / 256;
    const int eb  = (n4 + 255) / 256;           // epi blocks (same count)
    const int ab  = 4096;                       // agg grid-stride blocks
    const int pb  = (NN * 32 + 255) / 256;      // pool: warp per node

    // conv1: h = x @ W1
    gemm_kernel<<<dim3(gemmGridM, 1), 256>>>(x, W1, nullptr, bufA, NN, FIN, FH, 0);
    zero_f4<<<zb, 256>>>(bufB, n4);
    agg_kernel<<<ab, 256>>>(bufA, s, d, dinv, bufB, EE);
    epi_kernel<<<eb, 256>>>(bufA, bufB, dinv, b1, NN, 1);   // relu, in-place into bufA

    // conv2: h2 = h @ W2
    gemm_kernel<<<dim3(gemmGridM, 1), 256>>>(bufA, W2, nullptr, bufC, NN, FH, FH, 0);
    zero_f4<<<zb, 256>>>(bufB, n4);
    agg_kernel<<<ab, 256>>>(bufC, s, d, dinv, bufB, EE);
    epi_kernel<<<eb, 256>>>(bufC, bufB, dinv, b2, NN, 0);   // no relu

    pool_kernel<<<pb, 256>>>(bufC, batch, pool, NN, coloff);
}

extern "C" void kernel_launch(void* const* d_in, const int* in_sizes, int n_in,
                              void* d_out, int out_size) {
    const float* x     = (const float*)d_in[0];
    const int*   ei    = (const int*)d_in[1];
    const int*   batch = (const int*)d_in[2];
    // d_in[3] = num_graphs (unused; NG is compile-time)
    const float* td_W1 = (const float*)d_in[4];
    const float* td_b1 = (const float*)d_in[5];
    const float* td_W2 = (const float*)d_in[6];
    const float* td_b2 = (const float*)d_in[7];
    const float* bu_W1 = (const float*)d_in[8];
    const float* bu_b1 = (const float*)d_in[9];
    const float* bu_W2 = (const float*)d_in[10];
    const float* bu_b2 = (const float*)d_in[11];
    const float* pw1   = (const float*)d_in[12];
    const float* pb1   = (const float*)d_in[13];
    const float* pw2   = (const float*)d_in[14];
    const float* pb2   = (const float*)d_in[15];
    float* out = (float*)d_out;

    float *bufA, *bufB, *bufC, *pool, *mlp, *dinv;
    int* deg;
    cudaGetSymbolAddress((void**)&bufA, g_bufA);
    cudaGetSymbolAddress((void**)&bufB, g_bufB);
    cudaGetSymbolAddress((void**)&bufC, g_bufC);
    cudaGetSymbolAddress((void**)&pool, g_pool);
    cudaGetSymbolAddress((void**)&mlp,  g_mlp);
    cudaGetSymbolAddress((void**)&dinv, g_dinv);
    cudaGetSymbolAddress((void**)&deg,  g_deg);

    const int* src = ei;        // edge_index[0]
    const int* dst = ei + EE;   // edge_index[1]

    // degrees + dinv (both directions)
    zero_i<<<(2 * NN + 255) / 256, 256>>>(deg, 2 * NN);
    deg_kernel<<<(EE + 255) / 256, 256>>>(src, dst, deg, deg + NN, EE);
    dinv_kernel<<<(2 * NN + 255) / 256, 256>>>(deg, dinv, 2 * NN);

    // zero concat pool buffer [NG, 256]
    zero_f4<<<(NG * 64 + 255) / 256, 256>>>(pool, NG * 64);

    // TD branch: edges as given, deg over dst; result at cols [128,256)
    run_branch(x, src, dst, dinv, td_W1, td_b1, td_W2, td_b2, batch,
               bufA, bufB, bufC, pool, FH);
    // BU branch: edges flipped, deg over src; result at cols [0,128)
    run_branch(x, dst, src, dinv + NN, bu_W1, bu_b1, bu_W2, bu_b2, batch,
               bufA, bufB, bufC, pool, 0);

    // proj head: [512,256] -> relu -> [512,256] @ [256,128]
    gemm_kernel<<<dim3((NG + 63) / 64, 2), 256>>>(pool, pw1, pb1, mlp, NG, 256, 256, 1);
    gemm_kernel<<<dim3((NG + 63) / 64, 1), 256>>>(mlp, pw2, pb2, out, NG, 256, 128, 0);
}

// round 3
// speedup vs baseline: 3.1302x; 3.1302x over previous
#include <cuda_runtime.h>
#include <cstdint>

#define NN 50000
#define EE 800000
#define NG 512
#define FIN 256
#define FH 128

// ---------------- static device scratch ----------------
__device__ float g_buf1[NN * 256];        // 51.2 MB: GEMM1 out [N,256] (td|bu), later GEMM2 out
__device__ float g_bufTd[NN * FH];        // 25.6 MB: h1 td (post conv1)
__device__ float g_bufBu[NN * FH];        // 25.6 MB: h1 bu
__device__ float g_pool[NG * 256];        // concat pooled [G,256]: bu @0, td @128
__device__ float g_mlp[NG * 256];
__device__ int   g_deg[2 * NN];           // [0,NN)=indeg(dst) for td; [NN,2NN)=outdeg(src) for bu
__device__ float g_dinv[2 * NN];
__device__ int   g_off[2 * (NN + 1)];     // CSR offsets td | bu
__device__ int   g_cur[2 * NN];           // scatter cursors
__device__ int   g_csr[2 * EE];           // CSR adjacency td | bu
__device__ float g_W1cat[256 * 256];      // [td_W1 | bu_W1]

// ---------------- small utility kernels ----------------
__global__ void zero_f4(float* p, int n4) {
    int i = blockIdx.x * blockDim.x + threadIdx.x;
    if (i < n4) ((float4*)p)[i] = make_float4(0.f, 0.f, 0.f, 0.f);
}
__global__ void zero_i(int* p, int n) {
    int i = blockIdx.x * blockDim.x + threadIdx.x;
    if (i < n) p[i] = 0;
}
__global__ void deg_kernel(const int* __restrict__ src, const int* __restrict__ dst,
                           int* deg_in, int* deg_out, int e) {
    int i = blockIdx.x * blockDim.x + threadIdx.x;
    if (i < e) {
        atomicAdd(&deg_in[dst[i]], 1);
        atomicAdd(&deg_out[src[i]], 1);
    }
}
__global__ void dinv_kernel(const int* __restrict__ deg, float* __restrict__ dinv, int n) {
    int i = blockIdx.x * blockDim.x + threadIdx.x;
    if (i < n) dinv[i] = rsqrtf((float)deg[i] + 1.0f);
}

// Exclusive scan of deg -> off. One block per direction (blockIdx.x in {0,1}).
__global__ void scan2_kernel(const int* __restrict__ deg, int* __restrict__ off, int n) {
    const int sel = blockIdx.x;
    const int* d = deg + sel * n;
    int* o = off + sel * (n + 1);
    const int tid = threadIdx.x;
    const int chunk = (n + 1023) / 1024;
    const int base = tid * chunk;

    int sum = 0;
    for (int j = 0; j < chunk; j++) {
        int idx = base + j;
        if (idx < n) sum += d[idx];
    }
    __shared__ int part[1024];
    part[tid] = sum;
    __syncthreads();
    for (int s = 1; s < 1024; s <<= 1) {
        int v = 0;
        if (tid >= s) v = part[tid - s];
        __syncthreads();
        if (tid >= s) part[tid] += v;
        __syncthreads();
    }
    int running = part[tid] - sum;   // exclusive prefix of this thread's chunk
    for (int j = 0; j < chunk; j++) {
        int idx = base + j;
        if (idx < n) {
            o[idx] = running;
            running += d[idx];
        }
    }
    if (tid == 1023) o[n] = part[1023];
}

__global__ void setup_cursors(const int* __restrict__ off, int* __restrict__ cur, int n) {
    int i = blockIdx.x * blockDim.x + threadIdx.x;
    if (i < n) {
        cur[i]     = off[i];              // td
        cur[n + i] = off[(n + 1) + i];    // bu
    }
}

__global__ void scatter_kernel(const int* __restrict__ src, const int* __restrict__ dst,
                               int* cur_td, int* cur_bu,
                               int* __restrict__ csr_td, int* __restrict__ csr_bu, int e) {
    int i = blockIdx.x * blockDim.x + threadIdx.x;
    if (i < e) {
        int s = src[i], d = dst[i];
        csr_td[atomicAdd(&cur_td[d], 1)] = s;   // td: grouped by dst, stores src
        csr_bu[atomicAdd(&cur_bu[s], 1)] = d;   // bu: grouped by src, stores dst
    }
}

__global__ void cat_w1(const float* __restrict__ td, const float* __restrict__ bu,
                       float* __restrict__ out) {
    int i = blockIdx.x * blockDim.x + threadIdx.x;
    if (i < 256 * 128) {
        int r = i >> 7, c = i & 127;
        out[r * 256 + c]       = td[i];
        out[r * 256 + 128 + c] = bu[i];
    }
}

// ---------------- TF32 tensor-core GEMM ----------------
__device__ __forceinline__ uint32_t f2tf(float x) {
    uint32_t r;
    asm("cvt.rna.tf32.f32 %0, %1;" : "=r"(r) : "f"(x));
    return r;
}

// C[M, ldc-window] = A[M,K] @ B[K,ldb] (+bias, +relu). Block tile 128x128, kstep 32.
// 8 warps: warp tile 64(m) x 32(n) of m16n8k8 mma.
__global__ __launch_bounds__(256, 2)
void gemm_tf32(const float* __restrict__ A, const float* __restrict__ B,
               const float* __restrict__ bias, float* __restrict__ C,
               int M, int K, int ldb, int ldc, int relu) {
    __shared__ uint32_t As[32][136];   // [k][m], stride 136 (==8 mod 32) -> conflict-free frags
    __shared__ uint32_t Bs[32][136];   // [k][n]

    const int tid = threadIdx.x;
    const int lane = tid & 31;
    const int warp = tid >> 5;
    const int g = lane >> 2;      // groupID
    const int tig = lane & 3;     // threadID in group
    const int m0 = blockIdx.x * 128;
    const int n0 = blockIdx.y * 128;
    const int wm = (warp & 1) * 64;
    const int wn = (warp >> 1) * 32;

    float acc[4][4][4];
#pragma unroll
    for (int i = 0; i < 4; i++)
#pragma unroll
        for (int j = 0; j < 4; j++)
#pragma unroll
            for (int c = 0; c < 4; c++) acc[i][j][c] = 0.f;

    for (int k0 = 0; k0 < K; k0 += 32) {
        // A tile: warp w loads k-quad [4w,4w+4), m = lane + 32r  (transposed store)
#pragma unroll
        for (int r = 0; r < 4; r++) {
            int m = lane + 32 * r;
            int gm = m0 + m;
            float4 v = make_float4(0.f, 0.f, 0.f, 0.f);
            if (gm < M) v = *(const float4*)(A + (size_t)gm * K + k0 + warp * 4);
            As[warp * 4 + 0][m] = f2tf(v.x);
            As[warp * 4 + 1][m] = f2tf(v.y);
            As[warp * 4 + 2][m] = f2tf(v.z);
            As[warp * 4 + 3][m] = f2tf(v.w);
        }
        // B tile: 32k x 128n
#pragma unroll
        for (int l = 0; l < 4; l++) {
            int idx = tid + l * 256;
            int k = idx >> 5, nf = idx & 31;
            float4 v = *(const float4*)(B + (size_t)(k0 + k) * ldb + n0 + nf * 4);
            uint32_t* p = &Bs[k][nf * 4];
            p[0] = f2tf(v.x); p[1] = f2tf(v.y); p[2] = f2tf(v.z); p[3] = f2tf(v.w);
        }
        __syncthreads();

#pragma unroll
        for (int kk = 0; kk < 32; kk += 8) {
            uint32_t af[4][4], bf[4][2];
#pragma unroll
            for (int i = 0; i < 4; i++) {
                int mb = wm + i * 16 + g;
                af[i][0] = As[kk + tig][mb];
                af[i][1] = As[kk + tig][mb + 8];
                af[i][2] = As[kk + tig + 4][mb];
                af[i][3] = As[kk + tig + 4][mb + 8];
            }
#pragma unroll
            for (int j = 0; j < 4; j++) {
                int nb = wn + j * 8 + g;
                bf[j][0] = Bs[kk + tig][nb];
                bf[j][1] = Bs[kk + tig + 4][nb];
            }
#pragma unroll
            for (int i = 0; i < 4; i++)
#pragma unroll
                for (int j = 0; j < 4; j++) {
                    asm volatile(
                        "mma.sync.aligned.m16n8k8.row.col.f32.tf32.tf32.f32 "
                        "{%0,%1,%2,%3}, {%4,%5,%6,%7}, {%8,%9}, {%0,%1,%2,%3};"
                        : "+f"(acc[i][j][0]), "+f"(acc[i][j][1]),
                          "+f"(acc[i][j][2]), "+f"(acc[i][j][3])
                        : "r"(af[i][0]), "r"(af[i][1]), "r"(af[i][2]), "r"(af[i][3]),
                          "r"(bf[j][0]), "r"(bf[j][1]));
                }
        }
        __syncthreads();
    }

#pragma unroll
    for (int i = 0; i < 4; i++) {
        int r0 = m0 + wm + i * 16 + g;
        int r1 = r0 + 8;
#pragma unroll
        for (int j = 0; j < 4; j++) {
            int cb = n0 + wn + j * 8 + 2 * tig;
            float b0 = 0.f, b1 = 0.f;
            if (bias) { b0 = bias[cb]; b1 = bias[cb + 1]; }
            float v0 = acc[i][j][0] + b0, v1 = acc[i][j][1] + b1;
            float v2 = acc[i][j][2] + b0, v3 = acc[i][j][3] + b1;
            if (relu) {
                v0 = fmaxf(v0, 0.f); v1 = fmaxf(v1, 0.f);
                v2 = fmaxf(v2, 0.f); v3 = fmaxf(v3, 0.f);
            }
            if (r0 < M) { float2 t = make_float2(v0, v1); *(float2*)(C + (size_t)r0 * ldc + cb) = t; }
            if (r1 < M) { float2 t = make_float2(v2, v3); *(float2*)(C + (size_t)r1 * ldc + cb) = t; }
        }
    }
}

// ---------------- fused CSR aggregation + epilogue (+optional pooling) ----------------
// One warp per node. out[d] = act( dinv[d]*Σ dinv[s]·h[s] + dinv[d]²·h[d] + b )
__global__ void agg_csr(const float* __restrict__ h, int hs, int ho,
                        const int* __restrict__ csr, const int* __restrict__ off,
                        const float* __restrict__ dinv, const float* __restrict__ bias,
                        float* __restrict__ out, int os, int oo, int relu,
                        const int* __restrict__ batch, float* __restrict__ pool, int po) {
    int node = (blockIdx.x * blockDim.x + threadIdx.x) >> 5;
    if (node >= NN) return;
    int lane = threadIdx.x & 31;

    int e0 = off[node], e1 = off[node + 1];
    float4 acc = make_float4(0.f, 0.f, 0.f, 0.f);
    for (int j = e0; j < e1; j++) {
        int s = csr[j];                 // warp-uniform -> broadcast
        float w = dinv[s];
        float4 v = *(const float4*)(h + (size_t)s * hs + ho + lane * 4);
        acc.x = fmaf(w, v.x, acc.x);
        acc.y = fmaf(w, v.y, acc.y);
        acc.z = fmaf(w, v.z, acc.z);
        acc.w = fmaf(w, v.w, acc.w);
    }
    float di = dinv[node];
    float d2 = di * di;
    float4 sv = *(const float4*)(h + (size_t)node * hs + ho + lane * 4);
    float4 bv = *(const float4*)(bias + lane * 4);
    float4 r;
    r.x = fmaf(di, acc.x, fmaf(d2, sv.x, bv.x));
    r.y = fmaf(di, acc.y, fmaf(d2, sv.y, bv.y));
    r.z = fmaf(di, acc.z, fmaf(d2, sv.z, bv.z));
    r.w = fmaf(di, acc.w, fmaf(d2, sv.w, bv.w));
    if (relu) {
        r.x = fmaxf(r.x, 0.f); r.y = fmaxf(r.y, 0.f);
        r.z = fmaxf(r.z, 0.f); r.w = fmaxf(r.w, 0.f);
    }
    if (pool) {
        int gi = batch[node];
        float* p = pool + (size_t)gi * 256 + po + lane * 4;
        atomicAdd(p + 0, r.x);
        atomicAdd(p + 1, r.y);
        atomicAdd(p + 2, r.z);
        atomicAdd(p + 3, r.w);
    } else {
        *(float4*)(out + (size_t)node * os + oo + lane * 4) = r;
    }
}

// ---------------- launch ----------------
extern "C" void kernel_launch(void* const* d_in, const int* in_sizes, int n_in,
                              void* d_out, int out_size) {
    const float* x     = (const float*)d_in[0];
    const int*   ei    = (const int*)d_in[1];
    const int*   batch = (const int*)d_in[2];
    const float* td_W1 = (const float*)d_in[4];
    const float* td_b1 = (const float*)d_in[5];
    const float* td_W2 = (const float*)d_in[6];
    const float* td_b2 = (const float*)d_in[7];
    const float* bu_W1 = (const float*)d_in[8];
    const float* bu_b1 = (const float*)d_in[9];
    const float* bu_W2 = (const float*)d_in[10];
    const float* bu_b2 = (const float*)d_in[11];
    const float* pw1   = (const float*)d_in[12];
    const float* pb1   = (const float*)d_in[13];
    const float* pw2   = (const float*)d_in[14];
    const float* pb2   = (const float*)d_in[15];
    float* out = (float*)d_out;

    float *buf1, *bufTd, *bufBu, *pool, *mlp, *dinv, *W1cat;
    int *deg, *off, *cur, *csr;
    cudaGetSymbolAddress((void**)&buf1,  g_buf1);
    cudaGetSymbolAddress((void**)&bufTd, g_bufTd);
    cudaGetSymbolAddress((void**)&bufBu, g_bufBu);
    cudaGetSymbolAddress((void**)&pool,  g_pool);
    cudaGetSymbolAddress((void**)&mlp,   g_mlp);
    cudaGetSymbolAddress((void**)&dinv,  g_dinv);
    cudaGetSymbolAddress((void**)&W1cat, g_W1cat);
    cudaGetSymbolAddress((void**)&deg,   g_deg);
    cudaGetSymbolAddress((void**)&off,   g_off);
    cudaGetSymbolAddress((void**)&cur,   g_cur);
    cudaGetSymbolAddress((void**)&csr,   g_csr);

    const int* src = ei;
    const int* dst = ei + EE;
    const float* dinv_td = dinv;
    const float* dinv_bu = dinv + NN;
    const int* off_td = off;
    const int* off_bu = off + NN + 1;
    int* csr_td = csr;
    int* csr_bu = csr + EE;

    // --- graph structure (CSR both directions) ---
    zero_i<<<(2 * NN + 255) / 256, 256>>>(deg, 2 * NN);
    deg_kernel<<<(EE + 255) / 256, 256>>>(src, dst, deg, deg + NN, EE);
    dinv_kernel<<<(2 * NN + 255) / 256, 256>>>(deg, dinv, 2 * NN);
    scan2_kernel<<<2, 1024>>>(deg, off, NN);
    setup_cursors<<<(NN + 255) / 256, 256>>>(off, cur, NN);
    scatter_kernel<<<(EE + 255) / 256, 256>>>(src, dst, cur, cur + NN, csr_td, csr_bu, EE);

    // --- pool zero + concat W1 ---
    zero_f4<<<(NG * 64 + 255) / 256, 256>>>(pool, NG * 64);
    cat_w1<<<(256 * 128 + 255) / 256, 256>>>(td_W1, bu_W1, W1cat);

    const int gx = (NN + 127) / 128;   // 391
    const int aggBlocks = (NN * 32 + 255) / 256;

    // conv1 GEMM (both branches fused): buf1 = x @ [td_W1 | bu_W1]  -> [N,256]
    gemm_tf32<<<dim3(gx, 2), 256>>>(x, W1cat, nullptr, buf1, NN, 256, 256, 256, 0);

    // conv1 aggregation + bias + relu
    agg_csr<<<aggBlocks, 256>>>(buf1, 256, 0,   csr_td, off_td, dinv_td, td_b1,
                                bufTd, 128, 0, 1, nullptr, nullptr, 0);
    agg_csr<<<aggBlocks, 256>>>(buf1, 256, 128, csr_bu, off_bu, dinv_bu, bu_b1,
                                bufBu, 128, 0, 1, nullptr, nullptr, 0);

    // conv2 GEMMs -> reuse buf1 halves (ldc=256)
    gemm_tf32<<<dim3(gx, 1), 256>>>(bufTd, td_W2, nullptr, buf1,       NN, 128, 128, 256, 0);
    gemm_tf32<<<dim3(gx, 1), 256>>>(bufBu, bu_W2, nullptr, buf1 + 128, NN, 128, 128, 256, 0);

    // conv2 aggregation + bias, pooled directly into concat buffer [bu | td]
    agg_csr<<<aggBlocks, 256>>>(buf1, 256, 0,   csr_td, off_td, dinv_td, td_b2,
                                nullptr, 0, 0, 0, batch, pool, 128);
    agg_csr<<<aggBlocks, 256>>>(buf1, 256, 128, csr_bu, off_bu, dinv_bu, bu_b2,
                                nullptr, 0, 0, 0, batch, pool, 0);

    // MLP head
    gemm_tf32<<<dim3(4, 2), 256>>>(pool, pw1, pb1, mlp, NG, 256, 256, 256, 1);
    gemm_tf32<<<dim3(4, 1), 256>>>(mlp,  pw2, pb2, out, NG, 256, 128, 128, 0);
}